// round 4
// baseline (speedup 1.0000x reference)
#include <cuda_runtime.h>
#include <cuda_bf16.h>
#include <cstdint>

typedef __nv_bfloat16 bf16;

#define B_ 32
#define T_ 512
#define E_ 512
#define H_ 1024
#define O_ 128
#define G_ 4096
#define NCTA 128

// ---------------- scratch (static device globals; no allocs) ----------------
__device__ __align__(16) bf16  g_e[B_ * T_ * E_];          // gathered embeddings (bf16)
__device__ __align__(16) bf16  g_Wih[G_ * E_];             // W_ih bf16
__device__ __align__(16) bf16  g_Wp[NCTA * 32 * H_];       // W_hh packed per-CTA
__device__ __align__(16) bf16  g_Wo[O_ * H_];              // W_lin[:,H:2H]
__device__ __align__(16) bf16  g_Wv[O_ * H_];              // W_lin[:,0:H]
__device__ __align__(16) float g_xp[(size_t)T_ * B_ * G_]; // x_proj fp32 [T][B][4H]
__device__ __align__(16) bf16  g_hs[(size_t)B_ * T_ * H_]; // hidden states [B][T][H]
__device__ __align__(16) bf16  g_hbuf[2][B_ * H_];         // h double buffer
__device__ float g_vc[B_ * O_];                            // verb logits (+ b_lin)
__device__ int   g_cnt;
__device__ int   g_epoch;

// ---------------- PTX helpers ----------------
__device__ __forceinline__ uint32_t smem_u32(const void* p) {
    return (uint32_t)__cvta_generic_to_shared(p);
}
__device__ __forceinline__ void ldm_x4(uint32_t* r, uint32_t a) {
    asm volatile("ldmatrix.sync.aligned.m8n8.x4.shared.b16 {%0,%1,%2,%3}, [%4];"
                 : "=r"(r[0]), "=r"(r[1]), "=r"(r[2]), "=r"(r[3]) : "r"(a));
}
__device__ __forceinline__ void ldm_x2(uint32_t* r, uint32_t a) {
    asm volatile("ldmatrix.sync.aligned.m8n8.x2.shared.b16 {%0,%1}, [%2];"
                 : "=r"(r[0]), "=r"(r[1]) : "r"(a));
}
__device__ __forceinline__ void mma16816(float* d, const uint32_t* a, const uint32_t* b) {
    asm volatile(
        "mma.sync.aligned.m16n8k16.row.col.f32.bf16.bf16.f32 "
        "{%0,%1,%2,%3}, {%4,%5,%6,%7}, {%8,%9}, {%0,%1,%2,%3};\n"
        : "+f"(d[0]), "+f"(d[1]), "+f"(d[2]), "+f"(d[3])
        : "r"(a[0]), "r"(a[1]), "r"(a[2]), "r"(a[3]), "r"(b[0]), "r"(b[1]));
}
__device__ __forceinline__ void cpasync16(uint32_t s, const void* g) {
    asm volatile("cp.async.cg.shared.global [%0], [%1], 16;\n" :: "r"(s), "l"(g));
}
__device__ __forceinline__ void cp_commit() { asm volatile("cp.async.commit_group;\n"); }
template <int N> __device__ __forceinline__ void cp_wait() {
    asm volatile("cp.async.wait_group %0;\n" :: "n"(N));
}
__device__ __forceinline__ float sigmoidf_(float x) { return 1.f / (1.f + __expf(-x)); }

// ------------- prep1: init state + embedding gather (launch #0) -------------
__global__ void k_prep1(const int* __restrict__ tok, const float* __restrict__ emb) {
    int i = blockIdx.x * 256 + threadIdx.x;   // B*T*E/4 = 2,097,152 quads
    if (i == 0) { g_cnt = 0; g_epoch = 0; }
    if (i < 2 * B_ * H_ / 8) {                // zero h double buffer (uint4 granules)
        ((uint4*)g_hbuf)[i] = make_uint4(0, 0, 0, 0);
    }
    int m = i >> 7;                           // row in [0, B*T)
    int q = i & 127;
    int t = tok[m];
    float4 v = *(const float4*)(emb + (size_t)t * E_ + q * 4);
    __nv_bfloat162* d2 = (__nv_bfloat162*)(g_e + (size_t)m * E_ + q * 4);
    d2[0] = __floats2bfloat162_rn(v.x, v.y);
    d2[1] = __floats2bfloat162_rn(v.z, v.w);
}

// --- prep2: convert W_ih, pack W_hh per-CTA, split W_lin (launch #1) ---
__global__ void k_prep2(const float* __restrict__ wih, const float* __restrict__ whh,
                        const float* __restrict__ wlin) {
    const int n1 = G_ * E_ / 4;          // 524288 convert items (4 floats)
    const int n2 = NCTA * 32 * H_ / 8;   // 524288 pack items (8 elems)
    const int n3 = O_ * 2 * H_ / 4;      // 65536 split items (4 elems)
    int idx = blockIdx.x * 256 + threadIdx.x;   // grid covers max(n1,n2)
    if (idx < n1) {
        float4 v = ((const float4*)wih)[idx];
        ((__nv_bfloat162*)g_Wih)[2 * idx]     = __floats2bfloat162_rn(v.x, v.y);
        ((__nv_bfloat162*)g_Wih)[2 * idx + 1] = __floats2bfloat162_rn(v.z, v.w);
    }
    if (idx < n2) {
        int j = idx * 8;
        int k = j & (H_ - 1);
        int r = (j >> 10) & 31;
        int c = j >> 15;
        int row = (r >> 3) * H_ + c * 8 + (r & 7);
        const float* src = whh + (size_t)row * H_ + k;
        float4 a = *(const float4*)src;
        float4 b = *(const float4*)(src + 4);
        __nv_bfloat162 o[4];
        o[0] = __floats2bfloat162_rn(a.x, a.y);
        o[1] = __floats2bfloat162_rn(a.z, a.w);
        o[2] = __floats2bfloat162_rn(b.x, b.y);
        o[3] = __floats2bfloat162_rn(b.z, b.w);
        *(uint4*)(g_Wp + (size_t)j) = *(uint4*)o;
    }
    if (idx < n3) {
        int j = idx * 4;
        int o = j >> 11;
        int k = j & 2047;
        float4 v = *(const float4*)(wlin + j);
        __nv_bfloat162 p0 = __floats2bfloat162_rn(v.x, v.y);
        __nv_bfloat162 p1 = __floats2bfloat162_rn(v.z, v.w);
        bf16* dst = (k < H_) ? (g_Wv + o * H_ + k) : (g_Wo + o * H_ + (k - H_));
        ((__nv_bfloat162*)dst)[0] = p0;
        ((__nv_bfloat162*)dst)[1] = p1;
    }
}

// ---- bf16 NT mma GEMM, 2-stage cp.async: C[M,N] = A[M,K]*B[N,K]^T (+bias) ----
// BM=64 BN=64 BK=32, 128 threads (2x2 warps, 32x32 warp tile)
__global__ void __launch_bounds__(128) k_gemm(
    const bf16* __restrict__ A, const bf16* __restrict__ Bm, float* __restrict__ C,
    int M, int N, int K,
    const float* __restrict__ bias1, const float* __restrict__ bias2, int remap)
{
    __shared__ __align__(16) bf16 As[2][64 * 40];
    __shared__ __align__(16) bf16 Bs[2][64 * 40];
    const int tid = threadIdx.x, lane = tid & 31, w = tid >> 5;
    const int bm = blockIdx.x * 64, bn = blockIdx.y * 64;
    const int wm = (w & 1) * 32, wn = (w >> 1) * 32;

    float acc[2][4][4];
#pragma unroll
    for (int i = 0; i < 2; i++)
#pragma unroll
        for (int j = 0; j < 4; j++)
#pragma unroll
            for (int r = 0; r < 4; r++) acc[i][j][r] = 0.f;

    auto issue = [&](int k0, int s) {
#pragma unroll
        for (int c = tid; c < 256; c += 128) {
            int r = c >> 2, q = c & 3;
            cpasync16(smem_u32(&As[s][r * 40 + q * 8]),
                      A + (size_t)(bm + r) * K + k0 + q * 8);
            cpasync16(smem_u32(&Bs[s][r * 40 + q * 8]),
                      Bm + (size_t)(bn + r) * K + k0 + q * 8);
        }
        cp_commit();
    };

    const int NK = K / 32;
    issue(0, 0);
    for (int it = 0; it < NK; it++) {
        if (it + 1 < NK) issue((it + 1) * 32, (it + 1) & 1);
        else cp_commit();                 // empty group keeps wait count uniform
        cp_wait<1>();
        __syncthreads();
        const int s = it & 1;
#pragma unroll
        for (int kk = 0; kk < 32; kk += 16) {
            uint32_t af[2][4], bfr[4][2];
#pragma unroll
            for (int i = 0; i < 2; i++)
                ldm_x4(af[i], smem_u32(&As[s][(wm + i * 16 + (lane & 15)) * 40 + kk + (lane >> 4) * 8]));
#pragma unroll
            for (int j = 0; j < 2; j++) {
                int row = wn + j * 16 + (lane & 7) + ((lane >> 4) << 3);
                int col = kk + ((lane >> 3) & 1) * 8;
                uint32_t r4[4];
                ldm_x4(r4, smem_u32(&Bs[s][row * 40 + col]));
                bfr[j * 2][0] = r4[0]; bfr[j * 2][1] = r4[1];
                bfr[j * 2 + 1][0] = r4[2]; bfr[j * 2 + 1][1] = r4[3];
            }
#pragma unroll
            for (int i = 0; i < 2; i++)
#pragma unroll
                for (int j = 0; j < 4; j++) mma16816(acc[i][j], af[i], bfr[j]);
        }
        __syncthreads();
    }
#pragma unroll
    for (int i = 0; i < 2; i++)
#pragma unroll
        for (int j = 0; j < 4; j++) {
            int cN = bn + wn + j * 8 + (lane & 3) * 2;
            float bc0 = (bias1 ? bias1[cN] : 0.f) + (bias2 ? bias2[cN] : 0.f);
            float bc1 = (bias1 ? bias1[cN + 1] : 0.f) + (bias2 ? bias2[cN + 1] : 0.f);
#pragma unroll
            for (int p = 0; p < 2; p++) {
                int rr = bm + wm + i * 16 + (lane >> 2) + p * 8;
                int dst = remap ? ((rr & (T_ - 1)) * B_ + (rr >> 9)) : rr;
                C[(size_t)dst * N + cN]     = acc[i][j][2 * p + 0] + bc0;
                C[(size_t)dst * N + cN + 1] = acc[i][j][2 * p + 1] + bc1;
            }
        }
}

// ---------------- persistent recurrent LSTM kernel (launch #3) ----------------
// 128 CTAs x 256 threads (8 warps). CTA c owns h cols [8c,8c+8) and gate rows
// {g*H + 8c..8c+8}. h broadcast pipelined in 2 x 512-col chunks.
#define SMEM_LSTM (66048 * 2 + 4224)

__global__ void __launch_bounds__(256, 1) k_lstm() {
    extern __shared__ char smemraw[];
    bf16*  Ws    = (bf16*)smemraw;
    bf16*  As    = (bf16*)(smemraw + 66048);
    float* gates = (float*)(smemraw + 2 * 66048);
    const int tid = threadIdx.x, lane = tid & 31, w = tid >> 5;
    const int cta = blockIdx.x;
    const int wm = (w >> 2) * 16, wn = (w & 3) * 8;

    // W slice (32 rows x 1024) -> smem, stride 1032
    for (int i = tid; i < 4096; i += 256) {
        int r = i >> 7, q = i & 127;
        *(uint4*)&Ws[r * 1032 + q * 8] = *(const uint4*)(g_Wp + ((size_t)cta * 32 + r) * H_ + q * 8);
    }
    __syncthreads();

    const int b_i = tid >> 3, jl = tid & 7;
    const int gcol = cta * 8 + jl;
    // per-chunk (row, col-quad) map: 8 uint4 per thread, coalesced
    int hr[8], hq[8];
#pragma unroll
    for (int j = 0; j < 8; j++) { int idx = j * 256 + tid; hr[j] = idx >> 6; hq[j] = idx & 63; }
    float creg = 0.f;

    for (int t = 0; t < T_; t++) {
        const bf16* hsrc = g_hbuf[t & 1];
        const float* xrow = g_xp + (size_t)(t * B_ + b_i) * G_ + gcol;
        // prefetch this thread's 4 gate-bias values (DRAM, consumed at step end)
        float x0 = __ldcg(xrow);
        float x1 = __ldcg(xrow + H_);
        float x2 = __ldcg(xrow + 2 * H_);
        float x3 = __ldcg(xrow + 3 * H_);

        // chunk-0 h loads
        uint4 p[8];
#pragma unroll
        for (int j = 0; j < 8; j++)
            p[j] = __ldcg((const uint4*)(hsrc + (size_t)hr[j] * H_ + hq[j] * 8));

        float acc[4][4];
#pragma unroll
        for (int a = 0; a < 4; a++)
#pragma unroll
            for (int r = 0; r < 4; r++) acc[a][r] = 0.f;

#pragma unroll
        for (int j = 0; j < 8; j++)
            *(uint4*)&As[(size_t)hr[j] * 1032 + hq[j] * 8] = p[j];
        // issue chunk-1 loads (hidden behind chunk-0 mma)
#pragma unroll
        for (int j = 0; j < 8; j++)
            p[j] = __ldcg((const uint4*)(hsrc + (size_t)hr[j] * H_ + 512 + hq[j] * 8));
        __syncthreads();

#pragma unroll 8
        for (int kk = 0; kk < 512; kk += 16) {
            uint32_t af[4], bf2[2];
            ldm_x4(af, smem_u32(&As[(wm + (lane & 15)) * 1032 + kk + (lane >> 4) * 8]));
            ldm_x2(bf2, smem_u32(&Ws[(wn + (lane & 7)) * 1032 + kk + ((lane >> 3) & 1) * 8]));
            mma16816(acc[(kk >> 4) & 3], af, bf2);
        }
        // store chunk 1 (distinct smem region; no sync needed before STS)
#pragma unroll
        for (int j = 0; j < 8; j++)
            *(uint4*)&As[(size_t)hr[j] * 1032 + 512 + hq[j] * 8] = p[j];
        __syncthreads();

#pragma unroll 8
        for (int kk = 512; kk < 1024; kk += 16) {
            uint32_t af[4], bf2[2];
            ldm_x4(af, smem_u32(&As[(wm + (lane & 15)) * 1032 + kk + (lane >> 4) * 8]));
            ldm_x2(bf2, smem_u32(&Ws[(wn + (lane & 7)) * 1032 + kk + ((lane >> 3) & 1) * 8]));
            mma16816(acc[(kk >> 4) & 3], af, bf2);
        }

        float s0 = acc[0][0] + acc[1][0] + acc[2][0] + acc[3][0];
        float s1 = acc[0][1] + acc[1][1] + acc[2][1] + acc[3][1];
        float s2 = acc[0][2] + acc[1][2] + acc[2][2] + acc[3][2];
        float s3 = acc[0][3] + acc[1][3] + acc[2][3] + acc[3][3];
        int gr = wm + (lane >> 2), gc = wn + (lane & 3) * 2;
        gates[gr * 33 + gc]           = s0;
        gates[gr * 33 + gc + 1]       = s1;
        gates[(gr + 8) * 33 + gc]     = s2;
        gates[(gr + 8) * 33 + gc + 1] = s3;
        __syncthreads();

        // elementwise cell update for (batch b_i, column gcol)
        float pi = gates[b_i * 33 + jl]      + x0;
        float pf = gates[b_i * 33 + 8 + jl]  + x1;
        float pg = gates[b_i * 33 + 16 + jl] + x2;
        float po = gates[b_i * 33 + 24 + jl] + x3;
        float ig = sigmoidf_(pi), fg = sigmoidf_(pf), og = sigmoidf_(po);
        float gg = tanhf(pg);
        creg = fg * creg + ig * gg;
        float h = og * tanhf(creg);
        bf16 hb = __float2bfloat16(h);
        g_hbuf[(t + 1) & 1][b_i * H_ + gcol] = hb;
        g_hs[((size_t)b_i * T_ + t) * H_ + gcol] = hb;

        // grid barrier (epoch counting)
        __threadfence();
        __syncthreads();
        if (tid == 0) {
            int old = atomicAdd(&g_cnt, 1);
            if (old == NCTA - 1) {
                g_cnt = 0;
                __threadfence();
                atomicAdd(&g_epoch, 1);
            } else {
                while (*(volatile int*)&g_epoch < t + 1) __nanosleep(64);
            }
        }
        __syncthreads();
    }
}

// -------- verb logits: vc[b][o] = dot(hs[b,vidx[b],:], Wv[o,:]) + b_lin[o] --------
__global__ void k_vc(const int* __restrict__ vidx, const float* __restrict__ blin) {
    __shared__ bf16 vrow[H_];
    int b = blockIdx.x, tid = threadIdx.x;
    int t = vidx[b];
    for (int i = tid; i < H_; i += 128) vrow[i] = g_hs[((size_t)b * T_ + t) * H_ + i];
    __syncthreads();
    float s = 0.f;
    const bf16* wr = g_Wv + (size_t)tid * H_;
    for (int k = 0; k < H_; k += 2) {
        __nv_bfloat162 wv = *(const __nv_bfloat162*)(wr + k);
        __nv_bfloat162 hv = *(const __nv_bfloat162*)(vrow + k);
        s += __bfloat162float(wv.x) * __bfloat162float(hv.x)
           + __bfloat162float(wv.y) * __bfloat162float(hv.y);
    }
    g_vc[b * O_ + tid] = s + blin[tid];
}

// -------- fused add-verb-logits + log_softmax over O=128 --------
__global__ void k_lsm(float* __restrict__ out) {
    int m = blockIdx.x, tid = threadIdx.x, w = tid >> 5;
    int b = m >> 9;
    float x = out[(size_t)m * O_ + tid] + g_vc[b * O_ + tid];
    float mx = x;
#pragma unroll
    for (int o = 16; o; o >>= 1) mx = fmaxf(mx, __shfl_xor_sync(0xffffffffu, mx, o));
    __shared__ float s1[4], s2[4];
    if ((tid & 31) == 0) s1[w] = mx;
    __syncthreads();
    mx = fmaxf(fmaxf(s1[0], s1[1]), fmaxf(s1[2], s1[3]));
    float e = __expf(x - mx);
    float sm = e;
#pragma unroll
    for (int o = 16; o; o >>= 1) sm += __shfl_xor_sync(0xffffffffu, sm, o);
    if ((tid & 31) == 0) s2[w] = sm;
    __syncthreads();
    sm = s2[0] + s2[1] + s2[2] + s2[3];
    out[(size_t)m * O_ + tid] = x - mx - __logf(sm);
}

extern "C" void kernel_launch(void* const* d_in, const int* in_sizes, int n_in,
                              void* d_out, int out_size) {
    const int*   tokens = (const int*)d_in[0];
    const int*   vidx   = (const int*)d_in[1];
    const float* emb    = (const float*)d_in[2];
    const float* W_ih   = (const float*)d_in[3];
    const float* W_hh   = (const float*)d_in[4];
    const float* b_ih   = (const float*)d_in[5];
    const float* b_hh   = (const float*)d_in[6];
    const float* W_lin  = (const float*)d_in[7];
    const float* b_lin  = (const float*)d_in[8];
    float* out = (float*)d_out;

    static int smem_set = 0;
    if (!smem_set) {
        cudaFuncSetAttribute(k_lstm, cudaFuncAttributeMaxDynamicSharedMemorySize, SMEM_LSTM);
        smem_set = 1;
    }

    // launch #0: init + gather
    k_prep1<<<(B_ * T_ * E_ / 4) / 256, 256>>>(tokens, emb);
    // launch #1: weight conversions
    k_prep2<<<(G_ * E_ / 4) / 256, 256>>>(W_ih, W_hh, W_lin);
    // launch #2: x_proj GEMM -> g_xp [T][B][4H]
    {
        dim3 grid(16384 / 64, 4096 / 64);
        k_gemm<<<grid, 128>>>(g_e, g_Wih, g_xp, 16384, 4096, 512, b_ih, b_hh, 1);
    }
    // launch #3: persistent LSTM (target of ncu -s 5 -c 1)
    k_lstm<<<NCTA, 256, SMEM_LSTM>>>();
    // launch #4: out-part logits straight into d_out
    {
        dim3 grid(16384 / 64, 128 / 64);
        k_gemm<<<grid, 128>>>(g_hs, g_Wo, out, 16384, 128, 1024, nullptr, nullptr, 0);
    }
    // launch #5/#6: verb logits + fused log_softmax
    k_vc<<<B_, 128>>>(vidx, b_lin);
    k_lsm<<<B_ * T_, 128>>>(out);
}

// round 5
// speedup vs baseline: 7.8972x; 7.8972x over previous
#include <cuda_runtime.h>
#include <cuda_bf16.h>
#include <cstdint>

typedef __nv_bfloat16 bf16;

#define B_ 32
#define T_ 512
#define E_ 512
#define H_ 1024
#define O_ 128
#define NCTA 128
#define KTOT 1536          // 512 (e) + 1024 (h)
#define SW 1544            // smem row stride (elems); 1544*2B mod 128 = 16 -> conflict-free ldmatrix

// ---------------- scratch (static device globals; no allocs) ----------------
__device__ __align__(16) bf16  g_e[B_ * T_ * E_];              // embeddings bf16 [B][T][E]
__device__ __align__(16) bf16  g_Wc[(size_t)NCTA * 32 * KTOT]; // per-CTA [Wih|Whh] rows
__device__ __align__(16) bf16  g_Wo[O_ * H_];                  // W_lin[:,H:2H]
__device__ __align__(16) bf16  g_Wv[O_ * H_];                  // W_lin[:,0:H]
__device__ __align__(16) bf16  g_hs[(size_t)B_ * T_ * H_];     // hidden states [B][T][H]
__device__ __align__(16) bf16  g_hbuf[2][B_ * H_];             // h double buffer
__device__ float g_vc[B_ * O_];
__device__ int   g_arrive[NCTA];
__device__ int   g_epoch;

// ---------------- PTX helpers ----------------
__device__ __forceinline__ uint32_t smem_u32(const void* p) {
    return (uint32_t)__cvta_generic_to_shared(p);
}
__device__ __forceinline__ void ldm_x4(uint32_t* r, uint32_t a) {
    asm volatile("ldmatrix.sync.aligned.m8n8.x4.shared.b16 {%0,%1,%2,%3}, [%4];"
                 : "=r"(r[0]), "=r"(r[1]), "=r"(r[2]), "=r"(r[3]) : "r"(a));
}
__device__ __forceinline__ void mma16816(float* d, const uint32_t* a, const uint32_t* b) {
    asm volatile(
        "mma.sync.aligned.m16n8k16.row.col.f32.bf16.bf16.f32 "
        "{%0,%1,%2,%3}, {%4,%5,%6,%7}, {%8,%9}, {%0,%1,%2,%3};\n"
        : "+f"(d[0]), "+f"(d[1]), "+f"(d[2]), "+f"(d[3])
        : "r"(a[0]), "r"(a[1]), "r"(a[2]), "r"(a[3]), "r"(b[0]), "r"(b[1]));
}
__device__ __forceinline__ float sigmoidf_(float x) { return 1.f / (1.f + __expf(-x)); }

// ------------- prep1 (launch #0): init state + embedding gather -------------
__global__ void k_prep1(const int* __restrict__ tok, const float* __restrict__ emb) {
    int i = blockIdx.x * 256 + threadIdx.x;   // B*T*E/4 quads
    if (i == 0) g_epoch = 0;
    if (i < NCTA) g_arrive[i] = 0;
    if (i < 2 * B_ * H_ / 8) ((uint4*)g_hbuf)[i] = make_uint4(0, 0, 0, 0);
    int m = i >> 7;                           // row in [0, B*T)
    int q = i & 127;
    int t = tok[m];
    float4 v = *(const float4*)(emb + (size_t)t * E_ + q * 4);
    __nv_bfloat162* d2 = (__nv_bfloat162*)(g_e + (size_t)m * E_ + q * 4);
    d2[0] = __floats2bfloat162_rn(v.x, v.y);
    d2[1] = __floats2bfloat162_rn(v.z, v.w);
}

// ------- prep2 (launch #1): pack [W_ih | W_hh] gate rows per CTA -> g_Wc -------
__global__ void k_prep2(const float* __restrict__ wih, const float* __restrict__ whh) {
    int idx = blockIdx.x * 256 + threadIdx.x;          // NCTA*32*KTOT/8 items
    int j = idx * 8;
    int k = j % KTOT;
    int r = (j / KTOT) & 31;
    int c = j / (KTOT * 32);
    int row = (r >> 3) * H_ + c * 8 + (r & 7);
    const float* src = (k < E_) ? (wih + (size_t)row * E_ + k)
                                : (whh + (size_t)row * H_ + (k - E_));
    float4 a = *(const float4*)src;
    float4 b = *(const float4*)(src + 4);
    __nv_bfloat162 o[4];
    o[0] = __floats2bfloat162_rn(a.x, a.y);
    o[1] = __floats2bfloat162_rn(a.z, a.w);
    o[2] = __floats2bfloat162_rn(b.x, b.y);
    o[3] = __floats2bfloat162_rn(b.z, b.w);
    *(uint4*)(g_Wc + (size_t)j) = *(uint4*)o;
}

// ------------- prep3 (launch #2): split W_lin into Wv / Wo -------------
__global__ void k_prep3(const float* __restrict__ wlin) {
    int idx = blockIdx.x * 256 + threadIdx.x;   // O*2H/4 items
    int j = idx * 4;
    int o = j >> 11;
    int k = j & 2047;
    float4 v = *(const float4*)(wlin + j);
    __nv_bfloat162 p0 = __floats2bfloat162_rn(v.x, v.y);
    __nv_bfloat162 p1 = __floats2bfloat162_rn(v.z, v.w);
    bf16* dst = (k < H_) ? (g_Wv + o * H_ + k) : (g_Wo + o * H_ + (k - H_));
    ((__nv_bfloat162*)dst)[0] = p0;
    ((__nv_bfloat162*)dst)[1] = p1;
}

// ---------------- fused persistent LSTM (launch #3, profiled) ----------------
// 128 CTAs x 256 threads (8 warps). CTA c owns h cols [8c,8c+8) and the 32 gate
// rows {g*H + 8c+j}. gates = [e_t|h_t] @ Wc^T over K=1536; e-part mma runs in
// the grid-barrier shadow. Warps: (mw,nw,kw) = 2x2x2 (16m x 16n, K split 2-way).
// smem: Ws[32][SW] + As[32][SW] bf16 + gates[2][32][33] f32 = 206,080 B.
#define SMEM_LSTM (2 * 32 * SW * 2 + 2 * 32 * 33 * 4)

__global__ void __launch_bounds__(256, 1) k_lstm(const float* __restrict__ bih,
                                                 const float* __restrict__ bhh) {
    extern __shared__ char sm[];
    bf16*  Ws    = (bf16*)sm;
    bf16*  As    = (bf16*)(sm + 32 * SW * 2);
    float* gates = (float*)(sm + 2 * 32 * SW * 2);
    const int tid = threadIdx.x, lane = tid & 31, w = tid >> 5;
    const int cta = blockIdx.x;
    const int kw = w & 1, nw = (w >> 1) & 1, mw = w >> 2;
    const int b_i = tid >> 3, jl = tid & 7;
    const int gcol = cta * 8 + jl;

    // weight slice 32 x 1536 -> smem (stride SW)
    for (int i = tid; i < 6144; i += 256) {
        int r = i / 192, q = i - r * 192;
        *(uint4*)&Ws[r * SW + q * 8] = *(const uint4*)(g_Wc + ((size_t)cta * 32 + r) * KTOT + q * 8);
    }
    const float bs0 = bih[gcol]          + bhh[gcol];
    const float bs1 = bih[H_ + gcol]     + bhh[H_ + gcol];
    const float bs2 = bih[2 * H_ + gcol] + bhh[2 * H_ + gcol];
    const float bs3 = bih[3 * H_ + gcol] + bhh[3 * H_ + gcol];

    // fragment address components (constant across steps)
    const int arow = (mw * 16 + (lane & 15)) * SW + ((lane >> 4) * 8);
    const int brow = (nw * 16 + (lane & 7) + ((lane >> 4) << 3)) * SW + (((lane >> 3) & 1) * 8);

    float acc[2][2][4];
#pragma unroll
    for (int g = 0; g < 2; g++)
#pragma unroll
        for (int n = 0; n < 2; n++)
#pragma unroll
            for (int r = 0; r < 4; r++) acc[g][n][r] = 0.f;

    // e_0 -> smem, then e-mma for t=0
    uint4 ereg[8];
#pragma unroll
    for (int j = 0; j < 8; j++) {
        int idx = j * 256 + tid; int er = idx >> 6, eq = idx & 63;
        ereg[j] = *(const uint4*)(g_e + ((size_t)er * T_) * E_ + eq * 8);
    }
#pragma unroll
    for (int j = 0; j < 8; j++) {
        int idx = j * 256 + tid; int er = idx >> 6, eq = idx & 63;
        *(uint4*)&As[er * SW + eq * 8] = ereg[j];
    }
    __syncthreads();
    {
        const int kbe = kw * 256;
#pragma unroll 8
        for (int kk = 0; kk < 256; kk += 16) {
            uint32_t af[4], bb[4];
            ldm_x4(af, smem_u32(&As[arow + kbe + kk]));
            ldm_x4(bb, smem_u32(&Ws[brow + kbe + kk]));
            int g = (kk >> 4) & 1;
            mma16816(acc[g][0], af, bb);
            mma16816(acc[g][1], af, bb + 2);
        }
    }

    float creg = 0.f;
    for (int t = 0; t < T_; t++) {
        const bf16* hsrc = g_hbuf[t & 1];
        // load h [32][1024] (L2-coherent) and stage into As cols 512..1536
        uint4 hreg[16];
#pragma unroll
        for (int j = 0; j < 16; j++) {
            int idx = j * 256 + tid; int hr = idx >> 7, hq = idx & 127;
            hreg[j] = __ldcg((const uint4*)(hsrc + (size_t)hr * H_ + hq * 8));
        }
#pragma unroll
        for (int j = 0; j < 16; j++) {
            int idx = j * 256 + tid; int hr = idx >> 7, hq = idx & 127;
            *(uint4*)&As[hr * SW + 512 + hq * 8] = hreg[j];
        }
        __syncthreads();

        // prefetch e_{t+1} (no dependency; hides under h-mma)
        const int tn = (t + 1 < T_) ? t + 1 : T_ - 1;
#pragma unroll
        for (int j = 0; j < 8; j++) {
            int idx = j * 256 + tid; int er = idx >> 6, eq = idx & 63;
            ereg[j] = *(const uint4*)(g_e + ((size_t)er * T_ + tn) * E_ + eq * 8);
        }

        // h-part mma: 32 kk over cols [512 + kw*512, +512)
        const int kbh = 512 + kw * 512;
#pragma unroll 8
        for (int kk = 0; kk < 512; kk += 16) {
            uint32_t af[4], bb[4];
            ldm_x4(af, smem_u32(&As[arow + kbh + kk]));
            ldm_x4(bb, smem_u32(&Ws[brow + kbh + kk]));
            int g = (kk >> 4) & 1;
            mma16816(acc[g][0], af, bb);
            mma16816(acc[g][1], af, bb + 2);
        }

        // write gate partials (per-kw plane)
        {
            float* gp = gates + kw * (32 * 33);
            int gr = mw * 16 + (lane >> 2);
            int gcb = nw * 16 + (lane & 3) * 2;
#pragma unroll
            for (int n = 0; n < 2; n++) {
                gp[gr * 33 + gcb + n * 8]           = acc[0][n][0] + acc[1][n][0];
                gp[gr * 33 + gcb + n * 8 + 1]       = acc[0][n][1] + acc[1][n][1];
                gp[(gr + 8) * 33 + gcb + n * 8]     = acc[0][n][2] + acc[1][n][2];
                gp[(gr + 8) * 33 + gcb + n * 8 + 1] = acc[0][n][3] + acc[1][n][3];
            }
        }
        __syncthreads();

        // cell update for (batch b_i, column gcol)
        float pi = gates[b_i * 33 + jl]      + gates[32 * 33 + b_i * 33 + jl]      + bs0;
        float pf = gates[b_i * 33 + 8 + jl]  + gates[32 * 33 + b_i * 33 + 8 + jl]  + bs1;
        float pg = gates[b_i * 33 + 16 + jl] + gates[32 * 33 + b_i * 33 + 16 + jl] + bs2;
        float po = gates[b_i * 33 + 24 + jl] + gates[32 * 33 + b_i * 33 + 24 + jl] + bs3;
        float ig = sigmoidf_(pi), fg = sigmoidf_(pf), og = sigmoidf_(po);
        float gg = tanhf(pg);
        creg = fg * creg + ig * gg;
        float h = og * tanhf(creg);
        bf16 hb = __float2bfloat16(h);
        g_hbuf[(t + 1) & 1][b_i * H_ + gcol] = hb;
        g_hs[((size_t)b_i * T_ + t) * H_ + gcol] = hb;
        __threadfence();

        // stage e_{t+1} (all readers of As are past the gates sync)
#pragma unroll
        for (int j = 0; j < 8; j++) {
            int idx = j * 256 + tid; int er = idx >> 6, eq = idx & 63;
            *(uint4*)&As[er * SW + eq * 8] = ereg[j];
        }
        __syncthreads();                       // h stores fenced by all threads; e visible
        if (tid == 0) ((volatile int*)g_arrive)[cta] = t + 1;

        // e-part mma for t+1 — runs in the barrier shadow
#pragma unroll
        for (int g = 0; g < 2; g++)
#pragma unroll
            for (int n = 0; n < 2; n++)
#pragma unroll
                for (int r = 0; r < 4; r++) acc[g][n][r] = 0.f;
        const int kbe = kw * 256;
#pragma unroll 8
        for (int kk = 0; kk < 256; kk += 16) {
            uint32_t af[4], bb[4];
            ldm_x4(af, smem_u32(&As[arow + kbe + kk]));
            ldm_x4(bb, smem_u32(&Ws[brow + kbe + kk]));
            int g = (kk >> 4) & 1;
            mma16816(acc[g][0], af, bb);
            mma16816(acc[g][1], af, bb + 2);
        }

        // grid barrier: distinct flags + CTA0 collector (no atomic pile-up)
        if (cta == 0) {
            if (tid < NCTA) {
                while (((volatile int*)g_arrive)[tid] < t + 1) __nanosleep(32);
            }
            __syncthreads();
            if (tid == 0) { __threadfence(); *(volatile int*)&g_epoch = t + 1; }
        } else {
            if (tid == 0) {
                while (*(volatile int*)&g_epoch < t + 1) __nanosleep(32);
            }
        }
        __syncthreads();
    }
}

// -------- bf16 NT mma GEMM (sync loads, R3-proven): C = A*B^T (launch #4) --------
__global__ void __launch_bounds__(128) k_gemm(
    const bf16* __restrict__ A, const bf16* __restrict__ Bm, float* __restrict__ C,
    int M, int N, int K)
{
    __shared__ __align__(16) bf16 As2[64 * 40];
    __shared__ __align__(16) bf16 Bs2[64 * 40];
    const int tid = threadIdx.x, lane = tid & 31, w = tid >> 5;
    const int bm = blockIdx.x * 64, bn = blockIdx.y * 64;
    const int wm = (w & 1) * 32, wn = (w >> 1) * 32;

    float acc[2][4][4];
#pragma unroll
    for (int i = 0; i < 2; i++)
#pragma unroll
        for (int j = 0; j < 4; j++)
#pragma unroll
            for (int r = 0; r < 4; r++) acc[i][j][r] = 0.f;

    for (int k0 = 0; k0 < K; k0 += 32) {
#pragma unroll
        for (int c = tid; c < 256; c += 128) {
            int r = c >> 2, q = c & 3;
            *(uint4*)&As2[r * 40 + q * 8] = *(const uint4*)(A + (size_t)(bm + r) * K + k0 + q * 8);
            *(uint4*)&Bs2[r * 40 + q * 8] = *(const uint4*)(Bm + (size_t)(bn + r) * K + k0 + q * 8);
        }
        __syncthreads();
#pragma unroll
        for (int kk = 0; kk < 32; kk += 16) {
            uint32_t af[2][4], bfr[4][2];
#pragma unroll
            for (int i = 0; i < 2; i++)
                ldm_x4(af[i], smem_u32(&As2[(wm + i * 16 + (lane & 15)) * 40 + kk + (lane >> 4) * 8]));
#pragma unroll
            for (int j = 0; j < 2; j++) {
                int row = wn + j * 16 + (lane & 7) + ((lane >> 4) << 3);
                int col = kk + ((lane >> 3) & 1) * 8;
                uint32_t r4[4];
                ldm_x4(r4, smem_u32(&Bs2[row * 40 + col]));
                bfr[j * 2][0] = r4[0]; bfr[j * 2][1] = r4[1];
                bfr[j * 2 + 1][0] = r4[2]; bfr[j * 2 + 1][1] = r4[3];
            }
#pragma unroll
            for (int i = 0; i < 2; i++)
#pragma unroll
                for (int j = 0; j < 4; j++) mma16816(acc[i][j], af[i], bfr[j]);
        }
        __syncthreads();
    }
#pragma unroll
    for (int i = 0; i < 2; i++)
#pragma unroll
        for (int j = 0; j < 4; j++) {
            int cN = bn + wn + j * 8 + (lane & 3) * 2;
#pragma unroll
            for (int p = 0; p < 2; p++) {
                int rr = bm + wm + i * 16 + (lane >> 2) + p * 8;
                C[(size_t)rr * N + cN]     = acc[i][j][2 * p + 0];
                C[(size_t)rr * N + cN + 1] = acc[i][j][2 * p + 1];
            }
        }
}

// -------- verb logits (launch #5) --------
__global__ void k_vc(const int* __restrict__ vidx, const float* __restrict__ blin) {
    __shared__ bf16 vrow[H_];
    int b = blockIdx.x, tid = threadIdx.x;
    int t = vidx[b];
    for (int i = tid; i < H_; i += 128) vrow[i] = g_hs[((size_t)b * T_ + t) * H_ + i];
    __syncthreads();
    float s = 0.f;
    const bf16* wr = g_Wv + (size_t)tid * H_;
    for (int k = 0; k < H_; k += 2) {
        __nv_bfloat162 wv = *(const __nv_bfloat162*)(wr + k);
        __nv_bfloat162 hv = *(const __nv_bfloat162*)(vrow + k);
        s += __bfloat162float(wv.x) * __bfloat162float(hv.x)
           + __bfloat162float(wv.y) * __bfloat162float(hv.y);
    }
    g_vc[b * O_ + tid] = s + blin[tid];
}

// -------- fused add-verb-logits + log_softmax (launch #6) --------
__global__ void k_lsm(float* __restrict__ out) {
    int m = blockIdx.x, tid = threadIdx.x, w = tid >> 5;
    int b = m >> 9;
    float x = out[(size_t)m * O_ + tid] + g_vc[b * O_ + tid];
    float mx = x;
#pragma unroll
    for (int o = 16; o; o >>= 1) mx = fmaxf(mx, __shfl_xor_sync(0xffffffffu, mx, o));
    __shared__ float s1[4], s2[4];
    if ((tid & 31) == 0) s1[w] = mx;
    __syncthreads();
    mx = fmaxf(fmaxf(s1[0], s1[1]), fmaxf(s1[2], s1[3]));
    float e = __expf(x - mx);
    float sm = e;
#pragma unroll
    for (int o = 16; o; o >>= 1) sm += __shfl_xor_sync(0xffffffffu, sm, o);
    if ((tid & 31) == 0) s2[w] = sm;
    __syncthreads();
    sm = s2[0] + s2[1] + s2[2] + s2[3];
    out[(size_t)m * O_ + tid] = x - mx - __logf(sm);
}

extern "C" void kernel_launch(void* const* d_in, const int* in_sizes, int n_in,
                              void* d_out, int out_size) {
    const int*   tokens = (const int*)d_in[0];
    const int*   vidx   = (const int*)d_in[1];
    const float* emb    = (const float*)d_in[2];
    const float* W_ih   = (const float*)d_in[3];
    const float* W_hh   = (const float*)d_in[4];
    const float* b_ih   = (const float*)d_in[5];
    const float* b_hh   = (const float*)d_in[6];
    const float* W_lin  = (const float*)d_in[7];
    const float* b_lin  = (const float*)d_in[8];
    float* out = (float*)d_out;

    static int smem_set = 0;
    if (!smem_set) {
        cudaFuncSetAttribute(k_lstm, cudaFuncAttributeMaxDynamicSharedMemorySize, SMEM_LSTM);
        smem_set = 1;
    }

    // #0: init + gather
    k_prep1<<<(B_ * T_ * E_ / 4) / 256, 256>>>(tokens, emb);
    // #1: pack [W_ih|W_hh] per CTA
    k_prep2<<<(NCTA * 32 * KTOT / 8) / 256, 256>>>(W_ih, W_hh);
    // #2: split W_lin
    k_prep3<<<(O_ * 2 * H_ / 4) / 256, 256>>>(W_lin);
    // #3: fused persistent LSTM (profiled slot)
    k_lstm<<<NCTA, 256, SMEM_LSTM>>>(b_ih, b_hh);
    // #4: out-part logits straight into d_out
    {
        dim3 grid(16384 / 64, 128 / 64);
        k_gemm<<<grid, 128>>>(g_hs, g_Wo, out, 16384, 128, 1024);
    }
    // #5/#6: verb logits + fused log_softmax
    k_vc<<<B_, 128>>>(vidx, b_lin);
    k_lsm<<<B_ * T_, 128>>>(out);
}

// round 6
// speedup vs baseline: 8.9203x; 1.1295x over previous
#include <cuda_runtime.h>
#include <cuda_bf16.h>
#include <cstdint>

typedef __nv_bfloat16 bf16;

#define B_ 32
#define T_ 512
#define E_ 512
#define H_ 1024
#define O_ 128
#define NCTA 128
#define KTOT 1536          // 512 (e) + 1024 (h)
#define SW 1544            // smem row stride (elems); conflict-free ldmatrix

// ---------------- scratch (static device globals; no allocs) ----------------
__device__ __align__(16) bf16  g_e[B_ * T_ * E_];              // embeddings bf16 [B][T][E]
__device__ __align__(16) bf16  g_Wc[(size_t)NCTA * 32 * KTOT]; // per-CTA [Wih|Whh] rows
__device__ __align__(16) bf16  g_Wo[O_ * H_];                  // W_lin[:,H:2H]
__device__ __align__(16) bf16  g_Wv[O_ * H_];                  // W_lin[:,0:H]
__device__ __align__(16) bf16  g_hs[(size_t)B_ * T_ * H_];     // hidden states [B][T][H]
__device__ __align__(16) bf16  g_hbuf[2][B_ * H_];             // h double buffer
__device__ float g_vc[B_ * O_];
__device__ __align__(128) int g_arrive[NCTA * 32];             // 1 flag per CTA, 128B apart

// ---------------- PTX helpers ----------------
__device__ __forceinline__ uint32_t smem_u32(const void* p) {
    return (uint32_t)__cvta_generic_to_shared(p);
}
__device__ __forceinline__ void ldm_x4(uint32_t* r, uint32_t a) {
    asm volatile("ldmatrix.sync.aligned.m8n8.x4.shared.b16 {%0,%1,%2,%3}, [%4];"
                 : "=r"(r[0]), "=r"(r[1]), "=r"(r[2]), "=r"(r[3]) : "r"(a));
}
__device__ __forceinline__ void mma16816(float* d, const uint32_t* a, const uint32_t* b) {
    asm volatile(
        "mma.sync.aligned.m16n8k16.row.col.f32.bf16.bf16.f32 "
        "{%0,%1,%2,%3}, {%4,%5,%6,%7}, {%8,%9}, {%0,%1,%2,%3};\n"
        : "+f"(d[0]), "+f"(d[1]), "+f"(d[2]), "+f"(d[3])
        : "r"(a[0]), "r"(a[1]), "r"(a[2]), "r"(a[3]), "r"(b[0]), "r"(b[1]));
}
__device__ __forceinline__ float sigmoidf_(float x) { return 1.f / (1.f + __expf(-x)); }

// ------------- prep1 (launch #0): init state + embedding gather -------------
__global__ void k_prep1(const int* __restrict__ tok, const float* __restrict__ emb) {
    int i = blockIdx.x * 256 + threadIdx.x;   // B*T*E/4 quads
    if (i < NCTA * 32) g_arrive[i] = 0;
    if (i < 2 * B_ * H_ / 8) ((uint4*)g_hbuf)[i] = make_uint4(0, 0, 0, 0);
    int m = i >> 7;                           // row in [0, B*T)
    int q = i & 127;
    int t = tok[m];
    float4 v = *(const float4*)(emb + (size_t)t * E_ + q * 4);
    __nv_bfloat162* d2 = (__nv_bfloat162*)(g_e + (size_t)m * E_ + q * 4);
    d2[0] = __floats2bfloat162_rn(v.x, v.y);
    d2[1] = __floats2bfloat162_rn(v.z, v.w);
}

// ------- prep2 (launch #1): pack [W_ih | W_hh] gate rows per CTA -> g_Wc -------
__global__ void k_prep2(const float* __restrict__ wih, const float* __restrict__ whh) {
    int idx = blockIdx.x * 256 + threadIdx.x;          // NCTA*32*KTOT/8 items
    int j = idx * 8;
    int k = j % KTOT;
    int r = (j / KTOT) & 31;
    int c = j / (KTOT * 32);
    int row = (r >> 3) * H_ + c * 8 + (r & 7);
    const float* src = (k < E_) ? (wih + (size_t)row * E_ + k)
                                : (whh + (size_t)row * H_ + (k - E_));
    float4 a = *(const float4*)src;
    float4 b = *(const float4*)(src + 4);
    __nv_bfloat162 o[4];
    o[0] = __floats2bfloat162_rn(a.x, a.y);
    o[1] = __floats2bfloat162_rn(a.z, a.w);
    o[2] = __floats2bfloat162_rn(b.x, b.y);
    o[3] = __floats2bfloat162_rn(b.z, b.w);
    *(uint4*)(g_Wc + (size_t)j) = *(uint4*)o;
}

// ------------- prep3 (launch #2): split W_lin into Wv / Wo -------------
__global__ void k_prep3(const float* __restrict__ wlin) {
    int idx = blockIdx.x * 256 + threadIdx.x;   // O*2H/4 items
    int j = idx * 4;
    int o = j >> 11;
    int k = j & 2047;
    float4 v = *(const float4*)(wlin + j);
    __nv_bfloat162 p0 = __floats2bfloat162_rn(v.x, v.y);
    __nv_bfloat162 p1 = __floats2bfloat162_rn(v.z, v.w);
    bf16* dst = (k < H_) ? (g_Wv + o * H_ + k) : (g_Wo + o * H_ + (k - H_));
    ((__nv_bfloat162*)dst)[0] = p0;
    ((__nv_bfloat162*)dst)[1] = p1;
}

// ---------------- fused persistent LSTM (launch #3, profiled) ----------------
// 128 CTAs x 256 threads (8 warps). CTA c owns h cols [8c,8c+8) and the 32 gate
// rows {g*H + 8c+j}. gates = [e_t|h_t] @ Wc^T over K=1536; e-part mma runs in
// the grid-barrier shadow. Warps: (mw,nw,kw) = 2x2x2 (16m x 16n, K split 2-way).
// Barrier: release-store flag per CTA + direct all-to-all acquire polling.
#define SMEM_LSTM (2 * 32 * SW * 2 + 2 * 32 * 33 * 4)

__global__ void __launch_bounds__(256, 1) k_lstm(const float* __restrict__ bih,
                                                 const float* __restrict__ bhh) {
    extern __shared__ char sm[];
    bf16*  Ws    = (bf16*)sm;
    bf16*  As    = (bf16*)(sm + 32 * SW * 2);
    float* gates = (float*)(sm + 2 * 32 * SW * 2);
    const int tid = threadIdx.x, lane = tid & 31, w = tid >> 5;
    const int cta = blockIdx.x;
    const int kw = w & 1, nw = (w >> 1) & 1, mw = w >> 2;
    const int b_i = tid >> 3, jl = tid & 7;
    const int gcol = cta * 8 + jl;

    // weight slice 32 x 1536 -> smem (stride SW)
    for (int i = tid; i < 6144; i += 256) {
        int r = i / 192, q = i - r * 192;
        *(uint4*)&Ws[r * SW + q * 8] = *(const uint4*)(g_Wc + ((size_t)cta * 32 + r) * KTOT + q * 8);
    }
    const float bs0 = bih[gcol]          + bhh[gcol];
    const float bs1 = bih[H_ + gcol]     + bhh[H_ + gcol];
    const float bs2 = bih[2 * H_ + gcol] + bhh[2 * H_ + gcol];
    const float bs3 = bih[3 * H_ + gcol] + bhh[3 * H_ + gcol];

    // fragment address components (constant across steps)
    const int arow = (mw * 16 + (lane & 15)) * SW + ((lane >> 4) * 8);
    const int brow = (nw * 16 + (lane & 7) + ((lane >> 4) << 3)) * SW + (((lane >> 3) & 1) * 8);

    float acc[4][2][4];
#pragma unroll
    for (int g = 0; g < 4; g++)
#pragma unroll
        for (int n = 0; n < 2; n++)
#pragma unroll
            for (int r = 0; r < 4; r++) acc[g][n][r] = 0.f;

    // e_0 -> smem, then e-mma for t=0
    uint4 ereg[8];
#pragma unroll
    for (int j = 0; j < 8; j++) {
        int idx = j * 256 + tid; int er = idx >> 6, eq = idx & 63;
        ereg[j] = *(const uint4*)(g_e + ((size_t)er * T_) * E_ + eq * 8);
    }
#pragma unroll
    for (int j = 0; j < 8; j++) {
        int idx = j * 256 + tid; int er = idx >> 6, eq = idx & 63;
        *(uint4*)&As[er * SW + eq * 8] = ereg[j];
    }
    __syncthreads();
    {
        const int kbe = kw * 256;
#pragma unroll 8
        for (int kk = 0; kk < 256; kk += 16) {
            uint32_t af[4], bb[4];
            ldm_x4(af, smem_u32(&As[arow + kbe + kk]));
            ldm_x4(bb, smem_u32(&Ws[brow + kbe + kk]));
            int g = (kk >> 4) & 3;
            mma16816(acc[g][0], af, bb);
            mma16816(acc[g][1], af, bb + 2);
        }
    }

    float creg = 0.f;
    for (int t = 0; t < T_; t++) {
        const bf16* hsrc = g_hbuf[t & 1];
        // load h [32][1024] (L2-coherent) and stage into As cols 512..1536
        uint4 hreg[16];
#pragma unroll
        for (int j = 0; j < 16; j++) {
            int idx = j * 256 + tid; int hr = idx >> 7, hq = idx & 127;
            hreg[j] = __ldcg((const uint4*)(hsrc + (size_t)hr * H_ + hq * 8));
        }
#pragma unroll
        for (int j = 0; j < 16; j++) {
            int idx = j * 256 + tid; int hr = idx >> 7, hq = idx & 127;
            *(uint4*)&As[hr * SW + 512 + hq * 8] = hreg[j];
        }
        __syncthreads();

        // prefetch e_{t+1} (no dependency; hides under h-mma)
        const int tn = (t + 1 < T_) ? t + 1 : T_ - 1;
#pragma unroll
        for (int j = 0; j < 8; j++) {
            int idx = j * 256 + tid; int er = idx >> 6, eq = idx & 63;
            ereg[j] = *(const uint4*)(g_e + ((size_t)er * T_ + tn) * E_ + eq * 8);
        }

        // h-part mma: 32 kk over cols [512 + kw*512, +512), 4 accumulator chains
        const int kbh = 512 + kw * 512;
#pragma unroll 8
        for (int kk = 0; kk < 512; kk += 16) {
            uint32_t af[4], bb[4];
            ldm_x4(af, smem_u32(&As[arow + kbh + kk]));
            ldm_x4(bb, smem_u32(&Ws[brow + kbh + kk]));
            int g = (kk >> 4) & 3;
            mma16816(acc[g][0], af, bb);
            mma16816(acc[g][1], af, bb + 2);
        }

        // write gate partials (per-kw plane)
        {
            float* gp = gates + kw * (32 * 33);
            int gr = mw * 16 + (lane >> 2);
            int gcb = nw * 16 + (lane & 3) * 2;
#pragma unroll
            for (int n = 0; n < 2; n++) {
                gp[gr * 33 + gcb + n * 8]           = acc[0][n][0] + acc[1][n][0] + acc[2][n][0] + acc[3][n][0];
                gp[gr * 33 + gcb + n * 8 + 1]       = acc[0][n][1] + acc[1][n][1] + acc[2][n][1] + acc[3][n][1];
                gp[(gr + 8) * 33 + gcb + n * 8]     = acc[0][n][2] + acc[1][n][2] + acc[2][n][2] + acc[3][n][2];
                gp[(gr + 8) * 33 + gcb + n * 8 + 1] = acc[0][n][3] + acc[1][n][3] + acc[2][n][3] + acc[3][n][3];
            }
        }
        __syncthreads();

        // cell update for (batch b_i, column gcol)
        float pi = gates[b_i * 33 + jl]      + gates[32 * 33 + b_i * 33 + jl]      + bs0;
        float pf = gates[b_i * 33 + 8 + jl]  + gates[32 * 33 + b_i * 33 + 8 + jl]  + bs1;
        float pg = gates[b_i * 33 + 16 + jl] + gates[32 * 33 + b_i * 33 + 16 + jl] + bs2;
        float po = gates[b_i * 33 + 24 + jl] + gates[32 * 33 + b_i * 33 + 24 + jl] + bs3;
        float ig = sigmoidf_(pi), fg = sigmoidf_(pf), og = sigmoidf_(po);
        float gg = tanhf(pg);
        creg = fg * creg + ig * gg;
        float h = og * tanhf(creg);
        bf16 hb = __float2bfloat16(h);
        g_hbuf[(t + 1) & 1][b_i * H_ + gcol] = hb;
        g_hs[((size_t)b_i * T_ + t) * H_ + gcol] = hb;

        // stage e_{t+1} into As cols 0..511 (ldmatrix readers finished at gates sync)
#pragma unroll
        for (int j = 0; j < 8; j++) {
            int idx = j * 256 + tid; int er = idx >> 6, eq = idx & 63;
            *(uint4*)&As[er * SW + eq * 8] = ereg[j];
        }
        __syncthreads();   // all h stores + e staging done block-wide

        // release: one store publishes this CTA's h for step t+1
        if (tid == 0) {
            asm volatile("st.release.gpu.global.b32 [%0], %1;"
                         :: "l"(g_arrive + cta * 32), "r"(t + 1) : "memory");
        }

        // e-part mma for t+1 — runs in the barrier shadow
#pragma unroll
        for (int g = 0; g < 4; g++)
#pragma unroll
            for (int n = 0; n < 2; n++)
#pragma unroll
                for (int r = 0; r < 4; r++) acc[g][n][r] = 0.f;
        const int kbe = kw * 256;
#pragma unroll 8
        for (int kk = 0; kk < 256; kk += 16) {
            uint32_t af[4], bb[4];
            ldm_x4(af, smem_u32(&As[arow + kbe + kk]));
            ldm_x4(bb, smem_u32(&Ws[brow + kbe + kk]));
            int g = (kk >> 4) & 3;
            mma16816(acc[g][0], af, bb);
            mma16816(acc[g][1], af, bb + 2);
        }

        // single-hop all-to-all barrier: thread i polls CTA i's flag
        if (tid < NCTA) {
            const int* fp = g_arrive + tid * 32;
            int v;
            do {
                asm volatile("ld.acquire.gpu.global.b32 %0, [%1];" : "=r"(v) : "l"(fp));
            } while (v < t + 1);
        }
        __syncthreads();
    }
}

// -------- bf16 NT mma GEMM (sync loads): C = A*B^T (launch #4) --------
__global__ void __launch_bounds__(128) k_gemm(
    const bf16* __restrict__ A, const bf16* __restrict__ Bm, float* __restrict__ C,
    int M, int N, int K)
{
    __shared__ __align__(16) bf16 As2[64 * 40];
    __shared__ __align__(16) bf16 Bs2[64 * 40];
    const int tid = threadIdx.x, lane = tid & 31, w = tid >> 5;
    const int bm = blockIdx.x * 64, bn = blockIdx.y * 64;
    const int wm = (w & 1) * 32, wn = (w >> 1) * 32;

    float acc[2][4][4];
#pragma unroll
    for (int i = 0; i < 2; i++)
#pragma unroll
        for (int j = 0; j < 4; j++)
#pragma unroll
            for (int r = 0; r < 4; r++) acc[i][j][r] = 0.f;

    for (int k0 = 0; k0 < K; k0 += 32) {
#pragma unroll
        for (int c = tid; c < 256; c += 128) {
            int r = c >> 2, q = c & 3;
            *(uint4*)&As2[r * 40 + q * 8] = *(const uint4*)(A + (size_t)(bm + r) * K + k0 + q * 8);
            *(uint4*)&Bs2[r * 40 + q * 8] = *(const uint4*)(Bm + (size_t)(bn + r) * K + k0 + q * 8);
        }
        __syncthreads();
#pragma unroll
        for (int kk = 0; kk < 32; kk += 16) {
            uint32_t af[2][4], bfr[4][2];
#pragma unroll
            for (int i = 0; i < 2; i++)
                ldm_x4(af[i], smem_u32(&As2[(wm + i * 16 + (lane & 15)) * 40 + kk + (lane >> 4) * 8]));
#pragma unroll
            for (int j = 0; j < 2; j++) {
                int row = wn + j * 16 + (lane & 7) + ((lane >> 4) << 3);
                int col = kk + ((lane >> 3) & 1) * 8;
                uint32_t r4[4];
                ldm_x4(r4, smem_u32(&Bs2[row * 40 + col]));
                bfr[j * 2][0] = r4[0]; bfr[j * 2][1] = r4[1];
                bfr[j * 2 + 1][0] = r4[2]; bfr[j * 2 + 1][1] = r4[3];
            }
#pragma unroll
            for (int i = 0; i < 2; i++)
#pragma unroll
                for (int j = 0; j < 4; j++) mma16816(acc[i][j], af[i], bfr[j]);
        }
        __syncthreads();
    }
#pragma unroll
    for (int i = 0; i < 2; i++)
#pragma unroll
        for (int j = 0; j < 4; j++) {
            int cN = bn + wn + j * 8 + (lane & 3) * 2;
#pragma unroll
            for (int p = 0; p < 2; p++) {
                int rr = bm + wm + i * 16 + (lane >> 2) + p * 8;
                C[(size_t)rr * N + cN]     = acc[i][j][2 * p + 0];
                C[(size_t)rr * N + cN + 1] = acc[i][j][2 * p + 1];
            }
        }
}

// -------- verb logits (launch #5) --------
__global__ void k_vc(const int* __restrict__ vidx, const float* __restrict__ blin) {
    __shared__ bf16 vrow[H_];
    int b = blockIdx.x, tid = threadIdx.x;
    int t = vidx[b];
    for (int i = tid; i < H_; i += 128) vrow[i] = g_hs[((size_t)b * T_ + t) * H_ + i];
    __syncthreads();
    float s = 0.f;
    const bf16* wr = g_Wv + (size_t)tid * H_;
    for (int k = 0; k < H_; k += 2) {
        __nv_bfloat162 wv = *(const __nv_bfloat162*)(wr + k);
        __nv_bfloat162 hv = *(const __nv_bfloat162*)(vrow + k);
        s += __bfloat162float(wv.x) * __bfloat162float(hv.x)
           + __bfloat162float(wv.y) * __bfloat162float(hv.y);
    }
    g_vc[b * O_ + tid] = s + blin[tid];
}

// -------- fused add-verb-logits + log_softmax (launch #6) --------
__global__ void k_lsm(float* __restrict__ out) {
    int m = blockIdx.x, tid = threadIdx.x, w = tid >> 5;
    int b = m >> 9;
    float x = out[(size_t)m * O_ + tid] + g_vc[b * O_ + tid];
    float mx = x;
#pragma unroll
    for (int o = 16; o; o >>= 1) mx = fmaxf(mx, __shfl_xor_sync(0xffffffffu, mx, o));
    __shared__ float s1[4], s2[4];
    if ((tid & 31) == 0) s1[w] = mx;
    __syncthreads();
    mx = fmaxf(fmaxf(s1[0], s1[1]), fmaxf(s1[2], s1[3]));
    float e = __expf(x - mx);
    float sm = e;
#pragma unroll
    for (int o = 16; o; o >>= 1) sm += __shfl_xor_sync(0xffffffffu, sm, o);
    if ((tid & 31) == 0) s2[w] = sm;
    __syncthreads();
    sm = s2[0] + s2[1] + s2[2] + s2[3];
    out[(size_t)m * O_ + tid] = x - mx - __logf(sm);
}

extern "C" void kernel_launch(void* const* d_in, const int* in_sizes, int n_in,
                              void* d_out, int out_size) {
    const int*   tokens = (const int*)d_in[0];
    const int*   vidx   = (const int*)d_in[1];
    const float* emb    = (const float*)d_in[2];
    const float* W_ih   = (const float*)d_in[3];
    const float* W_hh   = (const float*)d_in[4];
    const float* b_ih   = (const float*)d_in[5];
    const float* b_hh   = (const float*)d_in[6];
    const float* W_lin  = (const float*)d_in[7];
    const float* b_lin  = (const float*)d_in[8];
    float* out = (float*)d_out;

    static int smem_set = 0;
    if (!smem_set) {
        cudaFuncSetAttribute(k_lstm, cudaFuncAttributeMaxDynamicSharedMemorySize, SMEM_LSTM);
        smem_set = 1;
    }

    // #0: init + gather
    k_prep1<<<(B_ * T_ * E_ / 4) / 256, 256>>>(tokens, emb);
    // #1: pack [W_ih|W_hh] per CTA
    k_prep2<<<(NCTA * 32 * KTOT / 8) / 256, 256>>>(W_ih, W_hh);
    // #2: split W_lin
    k_prep3<<<(O_ * 2 * H_ / 4) / 256, 256>>>(W_lin);
    // #3: fused persistent LSTM (profiled slot)
    k_lstm<<<NCTA, 256, SMEM_LSTM>>>(b_ih, b_hh);
    // #4: out-part logits straight into d_out
    {
        dim3 grid(16384 / 64, 128 / 64);
        k_gemm<<<grid, 128>>>(g_hs, g_Wo, out, 16384, 128, 1024);
    }
    // #5/#6: verb logits + fused log_softmax
    k_vc<<<B_, 128>>>(vidx, b_lin);
    k_lsm<<<B_ * T_, 128>>>(out);
}

// round 7
// speedup vs baseline: 10.2663x; 1.1509x over previous
#include <cuda_runtime.h>
#include <cuda_bf16.h>
#include <cstdint>

typedef __nv_bfloat16 bf16;

#define B_ 32
#define T_ 512
#define E_ 512
#define H_ 1024
#define O_ 128
#define NCTA 128
#define KTOT 1536          // 512 (e) + 1024 (h)
#define SW 1544            // As row stride (elems); 3088B % 128 = 16 -> conflict-free ldmatrix
#define SWE 520            // We row stride (elems); 1040B % 128 = 16 -> conflict-free
#define GST 40             // gates row stride (floats)

// ---------------- scratch (static device globals; no allocs) ----------------
__device__ __align__(16) bf16  g_e[B_ * T_ * E_];              // embeddings bf16 [B][T][E]
__device__ __align__(16) bf16  g_Wc[(size_t)NCTA * 32 * KTOT]; // per-CTA [Wih|Whh] rows
__device__ __align__(16) bf16  g_Wo[O_ * H_];                  // W_lin[:,H:2H]
__device__ __align__(16) bf16  g_Wv[O_ * H_];                  // W_lin[:,0:H]
__device__ __align__(16) bf16  g_hs[(size_t)B_ * T_ * H_];     // hidden states [B][T][H]
__device__ __align__(16) bf16  g_hbuf[2][B_ * H_];             // h double buffer
__device__ float g_vc[B_ * O_];
__device__ __align__(128) int g_arrive[NCTA * 32];             // 1 flag per CTA, 128B apart

// ---------------- PTX helpers ----------------
__device__ __forceinline__ uint32_t smem_u32(const void* p) {
    return (uint32_t)__cvta_generic_to_shared(p);
}
__device__ __forceinline__ void ldm_x4(uint32_t* r, uint32_t a) {
    asm volatile("ldmatrix.sync.aligned.m8n8.x4.shared.b16 {%0,%1,%2,%3}, [%4];"
                 : "=r"(r[0]), "=r"(r[1]), "=r"(r[2]), "=r"(r[3]) : "r"(a));
}
__device__ __forceinline__ void mma16816(float* d, const uint32_t* a, const uint32_t* b) {
    asm volatile(
        "mma.sync.aligned.m16n8k16.row.col.f32.bf16.bf16.f32 "
        "{%0,%1,%2,%3}, {%4,%5,%6,%7}, {%8,%9}, {%0,%1,%2,%3};\n"
        : "+f"(d[0]), "+f"(d[1]), "+f"(d[2]), "+f"(d[3])
        : "r"(a[0]), "r"(a[1]), "r"(a[2]), "r"(a[3]), "r"(b[0]), "r"(b[1]));
}
__device__ __forceinline__ float sigmoidf_(float x) { return 1.f / (1.f + __expf(-x)); }

// ------------- prep1 (launch #0): init state + embedding gather -------------
__global__ void k_prep1(const int* __restrict__ tok, const float* __restrict__ emb) {
    int i = blockIdx.x * 256 + threadIdx.x;   // B*T*E/4 quads
    if (i < NCTA * 32) g_arrive[i] = 0;
    if (i < 2 * B_ * H_ / 8) ((uint4*)g_hbuf)[i] = make_uint4(0, 0, 0, 0);
    int m = i >> 7;                           // row in [0, B*T)
    int q = i & 127;
    int t = tok[m];
    float4 v = *(const float4*)(emb + (size_t)t * E_ + q * 4);
    __nv_bfloat162* d2 = (__nv_bfloat162*)(g_e + (size_t)m * E_ + q * 4);
    d2[0] = __floats2bfloat162_rn(v.x, v.y);
    d2[1] = __floats2bfloat162_rn(v.z, v.w);
}

// ------- prep2 (launch #1): pack [W_ih | W_hh] gate rows per CTA -> g_Wc -------
__global__ void k_prep2(const float* __restrict__ wih, const float* __restrict__ whh) {
    int idx = blockIdx.x * 256 + threadIdx.x;          // NCTA*32*KTOT/8 items
    int j = idx * 8;
    int k = j % KTOT;
    int r = (j / KTOT) & 31;
    int c = j / (KTOT * 32);
    int row = (r >> 3) * H_ + c * 8 + (r & 7);
    const float* src = (k < E_) ? (wih + (size_t)row * E_ + k)
                                : (whh + (size_t)row * H_ + (k - E_));
    float4 a = *(const float4*)src;
    float4 b = *(const float4*)(src + 4);
    __nv_bfloat162 o[4];
    o[0] = __floats2bfloat162_rn(a.x, a.y);
    o[1] = __floats2bfloat162_rn(a.z, a.w);
    o[2] = __floats2bfloat162_rn(b.x, b.y);
    o[3] = __floats2bfloat162_rn(b.z, b.w);
    *(uint4*)(g_Wc + (size_t)j) = *(uint4*)o;
}

// ------------- prep3 (launch #2): split W_lin into Wv / Wo -------------
__global__ void k_prep3(const float* __restrict__ wlin) {
    int idx = blockIdx.x * 256 + threadIdx.x;   // O*2H/4 items
    int j = idx * 4;
    int o = j >> 11;
    int k = j & 2047;
    float4 v = *(const float4*)(wlin + j);
    __nv_bfloat162 p0 = __floats2bfloat162_rn(v.x, v.y);
    __nv_bfloat162 p1 = __floats2bfloat162_rn(v.z, v.w);
    bf16* dst = (k < H_) ? (g_Wv + o * H_ + k) : (g_Wo + o * H_ + (k - H_));
    ((__nv_bfloat162*)dst)[0] = p0;
    ((__nv_bfloat162*)dst)[1] = p1;
}

// ---------------- fused persistent LSTM (launch #3, profiled) ----------------
// 128 CTAs x 256 threads = 8 warps. Warp w owns the FULL n=32 gate-rows and a
// strided 1/8 of K: chunks c = w + 8j (j=0..11; j<4 -> e cols, j>=4 -> h cols).
// h-part weight fragments are REGISTER-RESIDENT across all 512 steps (bh[8][8]).
// e-part weights stay in smem (We) and are ldmatrix'd inside the barrier shadow.
// gates: 8 fp32 partial planes reduced in the cell update.
#define SMEM_LSTM (32 * SW * 2 + 32 * SWE * 2 + 8 * 32 * GST * 4)

__global__ void __launch_bounds__(256, 1) k_lstm(const float* __restrict__ bih,
                                                 const float* __restrict__ bhh) {
    extern __shared__ char sm[];
    bf16*  As    = (bf16*)sm;                               // 32 x SW
    bf16*  We    = (bf16*)(sm + 32 * SW * 2);               // 32 x SWE (e-weights)
    float* gates = (float*)(sm + 32 * SW * 2 + 32 * SWE * 2);
    const int tid = threadIdx.x, lane = tid & 31, w = tid >> 5;
    const int cta = blockIdx.x;
    const int b_i = tid >> 3, jl = tid & 7;
    const int gcol = cta * 8 + jl;

    // ---- init: full weight slice 32x1536 -> As (temporarily) ----
    for (int i = tid; i < 6144; i += 256) {
        int r = i / 192, q = i - r * 192;
        *(uint4*)&As[r * SW + q * 8] = *(const uint4*)(g_Wc + ((size_t)cta * 32 + r) * KTOT + q * 8);
    }
    __syncthreads();

    // hoist h-part B fragments to registers (j=4..11 -> chunks w+32..w+88)
    const int bro0 = ((lane & 7) + ((lane >> 4) << 3));
    const int bco  = ((lane >> 3) & 1) * 8;
    uint32_t bh[8][8];
#pragma unroll
    for (int j = 0; j < 8; j++) {
        int col = (w + 8 * (j + 4)) * 16;
#pragma unroll
        for (int nt = 0; nt < 2; nt++)
            ldm_x4(&bh[j][nt * 4], smem_u32(&As[(nt * 16 + bro0) * SW + col + bco]));
    }
    // e-part weights gmem -> We (32 x 512)
    for (int i = tid; i < 2048; i += 256) {
        int r = i >> 6, q = i & 63;
        *(uint4*)&We[r * SWE + q * 8] = *(const uint4*)(g_Wc + ((size_t)cta * 32 + r) * KTOT + q * 8);
    }
    const float bs0 = bih[gcol]          + bhh[gcol];
    const float bs1 = bih[H_ + gcol]     + bhh[H_ + gcol];
    const float bs2 = bih[2 * H_ + gcol] + bhh[2 * H_ + gcol];
    const float bs3 = bih[3 * H_ + gcol] + bhh[3 * H_ + gcol];
    __syncthreads();   // B frags read + We written before As reuse

    const int arow0 = (lane & 15) * SW + ((lane >> 4) * 8);

    float acc[2][4][4];
#pragma unroll
    for (int m = 0; m < 2; m++)
#pragma unroll
        for (int n = 0; n < 4; n++)
#pragma unroll
            for (int r = 0; r < 4; r++) acc[m][n][r] = 0.f;

    // ---- stage e_0, e-mma for t=0 ----
    uint4 ereg[8];
#pragma unroll
    for (int j = 0; j < 8; j++) {
        int idx = j * 256 + tid; int er = idx >> 6, eq = idx & 63;
        ereg[j] = *(const uint4*)(g_e + ((size_t)er * T_) * E_ + eq * 8);
    }
#pragma unroll
    for (int j = 0; j < 8; j++) {
        int idx = j * 256 + tid; int er = idx >> 6, eq = idx & 63;
        *(uint4*)&As[er * SW + eq * 8] = ereg[j];
    }
    __syncthreads();
#pragma unroll
    for (int j = 0; j < 4; j++) {
        int col = (w + 8 * j) * 16;
        uint32_t be[8];
        ldm_x4(be,     smem_u32(&We[(bro0) * SWE + col + bco]));
        ldm_x4(be + 4, smem_u32(&We[(16 + bro0) * SWE + col + bco]));
#pragma unroll
        for (int m = 0; m < 2; m++) {
            uint32_t af[4];
            ldm_x4(af, smem_u32(&As[m * 16 * SW + arow0 + col]));
            mma16816(acc[m][0], af, be);
            mma16816(acc[m][1], af, be + 2);
            mma16816(acc[m][2], af, be + 4);
            mma16816(acc[m][3], af, be + 6);
        }
    }

    float creg = 0.f;
    for (int t = 0; t < T_; t++) {
        const bf16* hsrc = g_hbuf[t & 1];
        // stage h [32][1024] into As cols 512..1536 (two waves of 8 uint4)
#pragma unroll
        for (int wave = 0; wave < 2; wave++) {
            uint4 hreg[8];
#pragma unroll
            for (int j = 0; j < 8; j++) {
                int idx = wave * 2048 + j * 256 + tid;
                int hr = idx >> 7, hq = idx & 127;
                hreg[j] = __ldcg((const uint4*)(hsrc + (size_t)hr * H_ + hq * 8));
            }
#pragma unroll
            for (int j = 0; j < 8; j++) {
                int idx = wave * 2048 + j * 256 + tid;
                int hr = idx >> 7, hq = idx & 127;
                *(uint4*)&As[hr * SW + 512 + hq * 8] = hreg[j];
            }
        }
        __syncthreads();

        // prefetch e_{t+1} (hidden under h-mma)
        const int tn = (t + 1 < T_) ? t + 1 : T_ - 1;
#pragma unroll
        for (int j = 0; j < 8; j++) {
            int idx = j * 256 + tid; int er = idx >> 6, eq = idx & 63;
            ereg[j] = *(const uint4*)(g_e + ((size_t)er * T_ + tn) * E_ + eq * 8);
        }

        // h-mma: 8 chunks, register-resident B
#pragma unroll
        for (int j = 0; j < 8; j++) {
            int col = (w + 8 * (j + 4)) * 16;
#pragma unroll
            for (int m = 0; m < 2; m++) {
                uint32_t af[4];
                ldm_x4(af, smem_u32(&As[m * 16 * SW + arow0 + col]));
                mma16816(acc[m][0], af, bh[j]);
                mma16816(acc[m][1], af, bh[j] + 2);
                mma16816(acc[m][2], af, bh[j] + 4);
                mma16816(acc[m][3], af, bh[j] + 6);
            }
        }

        // write gate partials to plane w
        {
            float* gp = gates + w * (32 * GST);
            int mr = lane >> 2, mc = (lane & 3) * 2;
#pragma unroll
            for (int m = 0; m < 2; m++)
#pragma unroll
                for (int n = 0; n < 4; n++) {
                    int row = m * 16 + mr, col = n * 8 + mc;
                    *(float2*)&gp[row * GST + col]       = make_float2(acc[m][n][0], acc[m][n][1]);
                    *(float2*)&gp[(row + 8) * GST + col] = make_float2(acc[m][n][2], acc[m][n][3]);
                }
        }
        __syncthreads();

        // cell update for (batch b_i, column gcol): reduce 8 planes
        float pi = bs0, pf = bs1, pg = bs2, po = bs3;
#pragma unroll
        for (int p = 0; p < 8; p++) {
            const float* gq = gates + p * (32 * GST) + b_i * GST;
            pi += gq[jl];
            pf += gq[8 + jl];
            pg += gq[16 + jl];
            po += gq[24 + jl];
        }
        float ig = sigmoidf_(pi), fg = sigmoidf_(pf), og = sigmoidf_(po);
        float gg = tanhf(pg);
        creg = fg * creg + ig * gg;
        float h = og * tanhf(creg);
        bf16 hb = __float2bfloat16(h);
        g_hbuf[(t + 1) & 1][b_i * H_ + gcol] = hb;
        g_hs[((size_t)b_i * T_ + t) * H_ + gcol] = hb;

        // stage e_{t+1} into As cols 0..511
#pragma unroll
        for (int j = 0; j < 8; j++) {
            int idx = j * 256 + tid; int er = idx >> 6, eq = idx & 63;
            *(uint4*)&As[er * SW + eq * 8] = ereg[j];
        }
        __syncthreads();   // h stores + e staging done block-wide

        // release: one store publishes this CTA's h for step t+1
        if (tid == 0) {
            asm volatile("st.release.gpu.global.b32 [%0], %1;"
                         :: "l"(g_arrive + cta * 32), "r"(t + 1) : "memory");
        }

        // e-part mma for t+1 — runs in the barrier shadow
#pragma unroll
        for (int m = 0; m < 2; m++)
#pragma unroll
            for (int n = 0; n < 4; n++)
#pragma unroll
                for (int r = 0; r < 4; r++) acc[m][n][r] = 0.f;
#pragma unroll
        for (int j = 0; j < 4; j++) {
            int col = (w + 8 * j) * 16;
            uint32_t be[8];
            ldm_x4(be,     smem_u32(&We[(bro0) * SWE + col + bco]));
            ldm_x4(be + 4, smem_u32(&We[(16 + bro0) * SWE + col + bco]));
#pragma unroll
            for (int m = 0; m < 2; m++) {
                uint32_t af[4];
                ldm_x4(af, smem_u32(&As[m * 16 * SW + arow0 + col]));
                mma16816(acc[m][0], af, be);
                mma16816(acc[m][1], af, be + 2);
                mma16816(acc[m][2], af, be + 4);
                mma16816(acc[m][3], af, be + 6);
            }
        }

        // single-hop all-to-all barrier: thread i polls CTA i's flag
        if (tid < NCTA) {
            const int* fp = g_arrive + tid * 32;
            int v;
            do {
                asm volatile("ld.acquire.gpu.global.b32 %0, [%1];" : "=r"(v) : "l"(fp));
            } while (v < t + 1);
        }
        __syncthreads();
    }
}

// -------- bf16 NT mma GEMM (sync loads): C = A*B^T (launch #4) --------
__global__ void __launch_bounds__(128) k_gemm(
    const bf16* __restrict__ A, const bf16* __restrict__ Bm, float* __restrict__ C,
    int M, int N, int K)
{
    __shared__ __align__(16) bf16 As2[64 * 40];
    __shared__ __align__(16) bf16 Bs2[64 * 40];
    const int tid = threadIdx.x, lane = tid & 31, w = tid >> 5;
    const int bm = blockIdx.x * 64, bn = blockIdx.y * 64;
    const int wm = (w & 1) * 32, wn = (w >> 1) * 32;

    float acc[2][4][4];
#pragma unroll
    for (int i = 0; i < 2; i++)
#pragma unroll
        for (int j = 0; j < 4; j++)
#pragma unroll
            for (int r = 0; r < 4; r++) acc[i][j][r] = 0.f;

    for (int k0 = 0; k0 < K; k0 += 32) {
#pragma unroll
        for (int c = tid; c < 256; c += 128) {
            int r = c >> 2, q = c & 3;
            *(uint4*)&As2[r * 40 + q * 8] = *(const uint4*)(A + (size_t)(bm + r) * K + k0 + q * 8);
            *(uint4*)&Bs2[r * 40 + q * 8] = *(const uint4*)(Bm + (size_t)(bn + r) * K + k0 + q * 8);
        }
        __syncthreads();
#pragma unroll
        for (int kk = 0; kk < 32; kk += 16) {
            uint32_t af[2][4], bfr[4][2];
#pragma unroll
            for (int i = 0; i < 2; i++)
                ldm_x4(af[i], smem_u32(&As2[(wm + i * 16 + (lane & 15)) * 40 + kk + (lane >> 4) * 8]));
#pragma unroll
            for (int j = 0; j < 2; j++) {
                int row = wn + j * 16 + (lane & 7) + ((lane >> 4) << 3);
                int col = kk + ((lane >> 3) & 1) * 8;
                uint32_t r4[4];
                ldm_x4(r4, smem_u32(&Bs2[row * 40 + col]));
                bfr[j * 2][0] = r4[0]; bfr[j * 2][1] = r4[1];
                bfr[j * 2 + 1][0] = r4[2]; bfr[j * 2 + 1][1] = r4[3];
            }
#pragma unroll
            for (int i = 0; i < 2; i++)
#pragma unroll
                for (int j = 0; j < 4; j++) mma16816(acc[i][j], af[i], bfr[j]);
        }
        __syncthreads();
    }
#pragma unroll
    for (int i = 0; i < 2; i++)
#pragma unroll
        for (int j = 0; j < 4; j++) {
            int cN = bn + wn + j * 8 + (lane & 3) * 2;
#pragma unroll
            for (int p = 0; p < 2; p++) {
                int rr = bm + wm + i * 16 + (lane >> 2) + p * 8;
                C[(size_t)rr * N + cN]     = acc[i][j][2 * p + 0];
                C[(size_t)rr * N + cN + 1] = acc[i][j][2 * p + 1];
            }
        }
}

// -------- verb logits (launch #5) --------
__global__ void k_vc(const int* __restrict__ vidx, const float* __restrict__ blin) {
    __shared__ bf16 vrow[H_];
    int b = blockIdx.x, tid = threadIdx.x;
    int t = vidx[b];
    for (int i = tid; i < H_; i += 128) vrow[i] = g_hs[((size_t)b * T_ + t) * H_ + i];
    __syncthreads();
    float s = 0.f;
    const uint4* wr4 = (const uint4*)(g_Wv + (size_t)tid * H_);
    const uint4* hv4 = (const uint4*)vrow;
#pragma unroll 4
    for (int k = 0; k < H_ / 8; k++) {
        uint4 wv = wr4[k];
        uint4 hv = hv4[k];
        const __nv_bfloat162* wp = (const __nv_bfloat162*)&wv;
        const __nv_bfloat162* hp = (const __nv_bfloat162*)&hv;
#pragma unroll
        for (int q = 0; q < 4; q++) {
            s += __bfloat162float(wp[q].x) * __bfloat162float(hp[q].x)
               + __bfloat162float(wp[q].y) * __bfloat162float(hp[q].y);
        }
    }
    g_vc[b * O_ + tid] = s + blin[tid];
}

// -------- fused add-verb-logits + log_softmax (launch #6) --------
__global__ void k_lsm(float* __restrict__ out) {
    int m = blockIdx.x, tid = threadIdx.x, w = tid >> 5;
    int b = m >> 9;
    float x = out[(size_t)m * O_ + tid] + g_vc[b * O_ + tid];
    float mx = x;
#pragma unroll
    for (int o = 16; o; o >>= 1) mx = fmaxf(mx, __shfl_xor_sync(0xffffffffu, mx, o));
    __shared__ float s1[4], s2[4];
    if ((tid & 31) == 0) s1[w] = mx;
    __syncthreads();
    mx = fmaxf(fmaxf(s1[0], s1[1]), fmaxf(s1[2], s1[3]));
    float e = __expf(x - mx);
    float sm = e;
#pragma unroll
    for (int o = 16; o; o >>= 1) sm += __shfl_xor_sync(0xffffffffu, sm, o);
    if ((tid & 31) == 0) s2[w] = sm;
    __syncthreads();
    sm = s2[0] + s2[1] + s2[2] + s2[3];
    out[(size_t)m * O_ + tid] = x - mx - __logf(sm);
}

extern "C" void kernel_launch(void* const* d_in, const int* in_sizes, int n_in,
                              void* d_out, int out_size) {
    const int*   tokens = (const int*)d_in[0];
    const int*   vidx   = (const int*)d_in[1];
    const float* emb    = (const float*)d_in[2];
    const float* W_ih   = (const float*)d_in[3];
    const float* W_hh   = (const float*)d_in[4];
    const float* b_ih   = (const float*)d_in[5];
    const float* b_hh   = (const float*)d_in[6];
    const float* W_lin  = (const float*)d_in[7];
    const float* b_lin  = (const float*)d_in[8];
    float* out = (float*)d_out;

    static int smem_set = 0;
    if (!smem_set) {
        cudaFuncSetAttribute(k_lstm, cudaFuncAttributeMaxDynamicSharedMemorySize, SMEM_LSTM);
        smem_set = 1;
    }

    // #0: init + gather
    k_prep1<<<(B_ * T_ * E_ / 4) / 256, 256>>>(tokens, emb);
    // #1: pack [W_ih|W_hh] per CTA
    k_prep2<<<(NCTA * 32 * KTOT / 8) / 256, 256>>>(W_ih, W_hh);
    // #2: split W_lin
    k_prep3<<<(O_ * 2 * H_ / 4) / 256, 256>>>(W_lin);
    // #3: fused persistent LSTM (profiled slot)
    k_lstm<<<NCTA, 256, SMEM_LSTM>>>(b_ih, b_hh);
    // #4: out-part logits straight into d_out
    {
        dim3 grid(16384 / 64, 128 / 64);
        k_gemm<<<grid, 128>>>(g_hs, g_Wo, out, 16384, 128, 1024);
    }
    // #5/#6: verb logits + fused log_softmax
    k_vc<<<B_, 128>>>(vidx, b_lin);
    k_lsm<<<B_ * T_, 128>>>(out);
}